// round 4
// baseline (speedup 1.0000x reference)
#include <cuda_runtime.h>

#define T_STEPS 2048
#define IN_DIM 32
#define HID 32
#define OUT_DIM 8

typedef unsigned long long ull;

// ---- packed fp32x2 helpers (sm_100+) ----
__device__ __forceinline__ void fma2(ull &d, ull a, ull b) {
    asm("fma.rn.f32x2 %0, %1, %2, %0;" : "+l"(d) : "l"(a), "l"(b));
}
__device__ __forceinline__ ull add2(ull a, ull b) {
    ull r; asm("add.rn.f32x2 %0, %1, %2;" : "=l"(r) : "l"(a), "l"(b)); return r;
}
__device__ __forceinline__ float red2(ull a) {
    float lo, hi;
    asm("mov.b64 {%0,%1}, %2;" : "=f"(lo), "=f"(hi) : "l"(a));
    return lo + hi;
}
// 16B shared load directly into two 64-bit regs (no repack movs)
__device__ __forceinline__ void lds2(ull &a, ull &b, unsigned addr) {
    asm volatile("ld.shared.v2.b64 {%0,%1}, [%2];" : "=l"(a), "=l"(b) : "r"(addr));
}

__device__ __forceinline__ float sigm(float x) {
    return __fdividef(1.0f, 1.0f + __expf(-x));
}
__device__ __forceinline__ float tanh_(float x) {
    // (e^{2x}-1)/(e^{2x}+1); clamp high side so e stays finite (tanh(15)==1 in fp32)
    float e = __expf(2.0f * fminf(x, 15.0f));
    return __fdividef(e - 1.0f, e + 1.0f);
}

// dot of a register-resident 32-wide row (16 packed pairs) with a 32-float smem vector
__device__ __forceinline__ void dot32(const ull *__restrict__ w, unsigned saddr,
                                      ull &a0, ull &a1, ull &a2, ull &a3) {
#pragma unroll
    for (int i = 0; i < 4; i++) {
        ull p0, p1, p2, p3;
        lds2(p0, p1, saddr + i * 32);
        lds2(p2, p3, saddr + i * 32 + 16);
        fma2(a0, w[4 * i + 0], p0);
        fma2(a1, w[4 * i + 1], p1);
        fma2(a2, w[4 * i + 2], p2);
        fma2(a3, w[4 * i + 3], p3);
    }
}

__global__ void __launch_bounds__(128, 2) lstm_kernel(
    const float *__restrict__ X,
    const float *__restrict__ Wih0, const float *__restrict__ Whh0,
    const float *__restrict__ bih0, const float *__restrict__ bhh0,
    const float *__restrict__ Wih1, const float *__restrict__ Whh1,
    const float *__restrict__ bih1, const float *__restrict__ bhh1,
    const float *__restrict__ Wfc, const float *__restrict__ bfc,
    float *__restrict__ out)
{
    __shared__ __align__(16) float xs[2][4][32];   // ping-pong tiles of 4 timesteps
    __shared__ __align__(16) float h1s[2][32];
    __shared__ __align__(16) float h2s[2][32];

    const int j = threadIdx.x;        // 0..127
    const int b = blockIdx.x;         // batch element
    const int gate = j & 3;           // 0=i 1=f 2=g 3=o
    const int u = j >> 2;             // hidden unit 0..31
    const int r = gate * 32 + u;      // row in the 128-row gate matrices
    const int lb = (j & 31) & ~3;     // lane base of this unit's 4-lane group

    // ---- register-resident fused weight rows: [Wih_row | Whh_row] as f32x2 pairs ----
    ull wA[32], wB[32];
    {
        const ull *p = (const ull *)(Wih0 + r * 32);
#pragma unroll
        for (int i = 0; i < 16; i++) wA[i] = p[i];
        p = (const ull *)(Whh0 + r * 32);
#pragma unroll
        for (int i = 0; i < 16; i++) wA[16 + i] = p[i];
        p = (const ull *)(Wih1 + r * 32);
#pragma unroll
        for (int i = 0; i < 16; i++) wB[i] = p[i];
        p = (const ull *)(Whh1 + r * 32);
#pragma unroll
        for (int i = 0; i < 16; i++) wB[16 + i] = p[i];
    }
    const float b1 = bih0[r] + bhh0[r];
    const float b2 = bih1[r] + bhh1[r];

    // ---- init state + x preload (tile 0 to smem, tile 1 to register) ----
    if (j < 32) { h1s[0][j] = 0.0f; h2s[0][j] = 0.0f; }
    const int q = j >> 5, lane = j & 31;
    const float *xb = X + (size_t)b * T_STEPS * IN_DIM;
    xs[0][q][lane] = xb[q * 32 + lane];
    float xr = xb[(4 + q) * 32 + lane];

    float c1 = 0.0f, c2 = 0.0f;

    const unsigned xs_base = (unsigned)__cvta_generic_to_shared(&xs[0][0][0]);
    const unsigned h1_base = (unsigned)__cvta_generic_to_shared(&h1s[0][0]);
    const unsigned h2_base = (unsigned)__cvta_generic_to_shared(&h2s[0][0]);

    __syncthreads();

#pragma unroll 2
    for (int t = 0; t < T_STEPS; t++) {
        const int p = t & 1;

        // ===== layer 1: gates = b1 + Wih0_row . x_t + Whh0_row . h1(t-1) =====
        ull a0 = 0ull, a1 = 0ull, a2 = 0ull, a3 = 0ull;
        const unsigned xaddr = xs_base + (unsigned)(((((t >> 2) & 1) << 2) + (t & 3)) << 7);
        dot32(wA, xaddr, a0, a1, a2, a3);
        dot32(wA + 16, h1_base + (p << 7), a0, a1, a2, a3);
        float g1 = red2(add2(add2(a0, a1), add2(a2, a3))) + b1;
        float act1 = (gate == 2) ? tanh_(g1) : sigm(g1);

        float vi = __shfl_sync(0xffffffffu, act1, lb + 0);
        float vf = __shfl_sync(0xffffffffu, act1, lb + 1);
        float vg = __shfl_sync(0xffffffffu, act1, lb + 2);
        float vo = __shfl_sync(0xffffffffu, act1, lb + 3);
        c1 = fmaf(vf, c1, vi * vg);
        float h1n = vo * tanh_(c1);
        if (gate == 0) h1s[p ^ 1][u] = h1n;
        __syncthreads();   // h1(t) visible

        // ===== layer 2: gates = b2 + Wih1_row . h1(t) + Whh1_row . h2(t-1) =====
        a0 = 0ull; a1 = 0ull; a2 = 0ull; a3 = 0ull;
        dot32(wB, h1_base + ((p ^ 1) << 7), a0, a1, a2, a3);
        dot32(wB + 16, h2_base + (p << 7), a0, a1, a2, a3);
        float g2 = red2(add2(add2(a0, a1), add2(a2, a3))) + b2;
        float act2 = (gate == 2) ? tanh_(g2) : sigm(g2);

        vi = __shfl_sync(0xffffffffu, act2, lb + 0);
        vf = __shfl_sync(0xffffffffu, act2, lb + 1);
        vg = __shfl_sync(0xffffffffu, act2, lb + 2);
        vo = __shfl_sync(0xffffffffu, act2, lb + 3);
        c2 = fmaf(vf, c2, vi * vg);
        float h2n = vo * tanh_(c2);
        if (gate == 0) h2s[p ^ 1][u] = h2n;

        // ===== x staging: every 4th step, commit prefetched tile, fetch next =====
        if ((t & 3) == 3) {
            int nt = (t >> 2) + 1;                 // tile in xr (timesteps 4nt..4nt+3)
            if (nt * 4 < T_STEPS) xs[nt & 1][q][lane] = xr;
            int f4 = (nt + 1) * 4;                 // next tile to fetch
            if (f4 < T_STEPS) xr = xb[(f4 + q) * 32 + lane];
        }
        __syncthreads();   // h2(t) + staged x visible
    }

    // ===== FC head on final h2 (last write was t=2047, p=1 -> buffer 0) =====
    if (j < OUT_DIM) {
        float s = bfc[j];
        const float *w = Wfc + j * HID;
#pragma unroll
        for (int k = 0; k < HID; k++) s = fmaf(w[k], h2s[0][k], s);
        out[b * OUT_DIM + j] = s;
    }
}

extern "C" void kernel_launch(void* const* d_in, const int* in_sizes, int n_in,
                              void* d_out, int out_size) {
    (void)in_sizes; (void)n_in; (void)out_size;
    lstm_kernel<<<512, 128>>>(
        (const float*)d_in[0],
        (const float*)d_in[1], (const float*)d_in[2],
        (const float*)d_in[3], (const float*)d_in[4],
        (const float*)d_in[5], (const float*)d_in[6],
        (const float*)d_in[7], (const float*)d_in[8],
        (const float*)d_in[9], (const float*)d_in[10],
        (float*)d_out);
}